// round 1
// baseline (speedup 1.0000x reference)
#include <cuda_runtime.h>

#define BATCH   65536
#define DIM     128
#define NPROTO  512
#define ODIM    8

#define MTILE   128
#define NTILE   128
#define XSTR    129   // padded stride for transposed x tile (odd*? -> 4-way max conflict on store)

// Scratch (allocation-free rule: __device__ globals)
__device__ __align__(16) float g_wT[DIM * NPROTO];   // wT[d][p] = r2[d] * proto[p][d]
__device__ __align__(16) float g_bias[NPROTO];       // -0.5 * sum_d r2[d] * proto[p][d]^2

// ---------------------------------------------------------------------------
// Prep: build transposed weighted prototypes + bias
// ---------------------------------------------------------------------------
__global__ void prep_kernel(const float* __restrict__ protos,
                            const float* __restrict__ relevance) {
    int p = blockIdx.x;          // 512 blocks
    int d = threadIdx.x;         // 128 threads
    float r  = relevance[d];
    float r2 = r * r;
    float pv = protos[p * DIM + d];
    float w  = r2 * pv;
    g_wT[d * NPROTO + p] = w;

    float part = w * pv;
    __shared__ float red[4];
    #pragma unroll
    for (int off = 16; off > 0; off >>= 1)
        part += __shfl_down_sync(0xffffffffu, part, off);
    if ((d & 31) == 0) red[d >> 5] = part;
    __syncthreads();
    if (d == 0) g_bias[p] = -0.5f * (red[0] + red[1] + red[2] + red[3]);
}

// ---------------------------------------------------------------------------
// Main: tiled GEMM (x @ wT) + fused argmax + gather of prototype_outputs
//   CTA: 128 rows x (4 chunks of 128 protos), 256 threads, 8x8 reg tile.
//   Accumulators are f32x2 pairs over the N dimension (FFMA2).
// ---------------------------------------------------------------------------
extern __shared__ float smem[];

__global__ void __launch_bounds__(256, 1)
grlvq_main(const float* __restrict__ x,
           const float* __restrict__ proto_out,
           float* __restrict__ out) {
    float* xs = smem;                   // [DIM][XSTR]  (x tile, transposed)
    float* ws = smem + DIM * XSTR;      // [DIM][NTILE] (w chunk, k-major)

    const int tid = threadIdx.x;
    const int tx  = tid & 15;           // -> 8 protos
    const int ty  = tid >> 4;           // -> 8 rows
    const int m0  = ty * 8;
    const int n0  = tx * 8;
    const int row0 = blockIdx.x * MTILE;

    // ---- load x tile, transposed into xs[d][m] ----
    const float4* x4 = (const float4*)(x + (size_t)row0 * DIM);
    for (int i = tid; i < MTILE * (DIM / 4); i += 256) {
        int r  = i >> 5;                // row in tile
        int c4 = i & 31;                // float4 column
        float4 v = x4[r * (DIM / 4) + c4];
        int d = c4 * 4;
        xs[(d + 0) * XSTR + r] = v.x;
        xs[(d + 1) * XSTR + r] = v.y;
        xs[(d + 2) * XSTR + r] = v.z;
        xs[(d + 3) * XSTR + r] = v.w;
    }

    float bestv[8];
    int   besti[8];
    #pragma unroll
    for (int i = 0; i < 8; i++) { bestv[i] = -3.402823466e38f; besti[i] = 0; }

    for (int ch = 0; ch < NPROTO / NTILE; ch++) {
        __syncthreads();
        // ---- load w chunk: ws[k][n] = g_wT[k*NPROTO + ch*NTILE + n] (coalesced) ----
        const float4* w4  = (const float4*)g_wT;
        float4*       ws4 = (float4*)ws;
        for (int i = tid; i < DIM * (NTILE / 4); i += 256) {
            int k  = i >> 5;
            int n4 = i & 31;
            ws4[k * (NTILE / 4) + n4] =
                w4[k * (NPROTO / 4) + ch * (NTILE / 4) + n4];
        }
        __syncthreads();

        unsigned long long acc[8][4];
        #pragma unroll
        for (int m = 0; m < 8; m++)
            #pragma unroll
            for (int j = 0; j < 4; j++) acc[m][j] = 0ULL;

        #pragma unroll 4
        for (int k = 0; k < DIM; k++) {
            const float* xr = &xs[k * XSTR + m0];
            const unsigned long long* bp =
                (const unsigned long long*)&ws[k * NTILE + n0];
            unsigned long long b0 = bp[0], b1 = bp[1], b2 = bp[2], b3 = bp[3];
            #pragma unroll
            for (int m = 0; m < 8; m++) {
                float av = xr[m];                 // broadcast LDS
                unsigned long long a2;
                asm("mov.b64 %0, {%1, %1};" : "=l"(a2) : "f"(av));
                asm("fma.rn.f32x2 %0, %1, %2, %0;" : "+l"(acc[m][0]) : "l"(a2), "l"(b0));
                asm("fma.rn.f32x2 %0, %1, %2, %0;" : "+l"(acc[m][1]) : "l"(a2), "l"(b1));
                asm("fma.rn.f32x2 %0, %1, %2, %0;" : "+l"(acc[m][2]) : "l"(a2), "l"(b2));
                asm("fma.rn.f32x2 %0, %1, %2, %0;" : "+l"(acc[m][3]) : "l"(a2), "l"(b3));
            }
        }

        // ---- bias + running argmax (ascending n => strict '>' keeps lowest idx) ----
        const int nb = ch * NTILE + n0;
        float bias[8];
        #pragma unroll
        for (int j = 0; j < 8; j++) bias[j] = __ldg(&g_bias[nb + j]);
        #pragma unroll
        for (int m = 0; m < 8; m++) {
            #pragma unroll
            for (int j = 0; j < 4; j++) {
                float lo = __uint_as_float((unsigned)(acc[m][j] & 0xffffffffULL));
                float hi = __uint_as_float((unsigned)(acc[m][j] >> 32));
                float slo = lo + bias[2 * j];
                float shi = hi + bias[2 * j + 1];
                if (slo > bestv[m]) { bestv[m] = slo; besti[m] = nb + 2 * j; }
                if (shi > bestv[m]) { bestv[m] = shi; besti[m] = nb + 2 * j + 1; }
            }
        }
    }

    // ---- cross-thread reduction over tx (16 candidates per row) ----
    __syncthreads();
    float* redv = smem;                      // 128*16 floats (reuse xs area)
    int*   redi = (int*)(smem + MTILE * 16); // 128*16 ints
    #pragma unroll
    for (int m = 0; m < 8; m++) {
        redv[(m0 + m) * 16 + tx] = bestv[m];
        redi[(m0 + m) * 16 + tx] = besti[m];
    }
    __syncthreads();

    if (tid < MTILE) {
        float bv = redv[tid * 16];
        int   bi = redi[tid * 16];
        #pragma unroll
        for (int j = 1; j < 16; j++) {
            float v  = redv[tid * 16 + j];
            int   ix = redi[tid * 16 + j];
            if (v > bv || (v == bv && ix < bi)) { bv = v; bi = ix; }
        }
        const float4* po4 = (const float4*)proto_out;
        float4* o4 = (float4*)(out + (size_t)(row0 + tid) * ODIM);
        o4[0] = po4[bi * 2];
        o4[1] = po4[bi * 2 + 1];
    }
}

// ---------------------------------------------------------------------------
extern "C" void kernel_launch(void* const* d_in, const int* in_sizes, int n_in,
                              void* d_out, int out_size) {
    const float* x         = (const float*)d_in[0];  // [65536,128]
    const float* protos    = (const float*)d_in[1];  // [512,128]
    const float* proto_out = (const float*)d_in[2];  // [512,8]
    const float* relevance = (const float*)d_in[3];  // [128]
    float* out = (float*)d_out;                      // [65536,8]

    prep_kernel<<<NPROTO, DIM>>>(protos, relevance);

    const int smem_bytes = (DIM * XSTR + DIM * NTILE) * (int)sizeof(float); // 131584
    cudaFuncSetAttribute(grlvq_main,
                         cudaFuncAttributeMaxDynamicSharedMemorySize, smem_bytes);
    grlvq_main<<<BATCH / MTILE, 256, smem_bytes>>>(x, proto_out, out);
}

// round 3
// speedup vs baseline: 1.4566x; 1.4566x over previous
#include <cuda_runtime.h>
#include <cuda_bf16.h>
#include <cstdint>

#define BATCH   65536
#define DIM     128
#define NPROTO  512
#define ODIM    8
#define MTILE   128
#define NCHUNK  64
#define NCHUNKS 8

#define ASTRIDE 272                    // bytes per smem row (136 bf16, conflict-free ldmatrix)
#define ASPLIT  (MTILE * ASTRIDE)      // 34816 per split matrix
#define MATB    (NCHUNK * ASTRIDE)     // 17408 per B split matrix
#define BBUF    (3 * MATB)             // 52224 per B buffer

#define SM_BIAS 0
#define SM_A    2048
#define SM_B    (SM_A + 3 * ASPLIT)    // 106496
#define SM_RED  SM_A
#define SMEM_TOTAL (SM_B + 2 * BBUF)   // 210944

__device__ __align__(16) __nv_bfloat16 g_w[3][NPROTO * DIM];  // h/m/l of r^2*proto, [p][d]
__device__ float g_bias[NPROTO];

// ---------------- helpers ----------------
__device__ __forceinline__ uint32_t smem_u32(const void* p) {
    uint32_t a;
    asm("{ .reg .u64 t; cvta.to.shared.u64 t, %1; cvt.u32.u64 %0, t; }" : "=r"(a) : "l"(p));
    return a;
}
__device__ __forceinline__ void ldsm4(uint32_t* r, uint32_t a) {
    asm volatile("ldmatrix.sync.aligned.m8n8.x4.shared.b16 {%0,%1,%2,%3}, [%4];"
                 : "=r"(r[0]), "=r"(r[1]), "=r"(r[2]), "=r"(r[3]) : "r"(a));
}
__device__ __forceinline__ void mma16816(float* d, const uint32_t* a, const uint32_t* b) {
    asm volatile(
        "mma.sync.aligned.m16n8k16.row.col.f32.bf16.bf16.f32 "
        "{%0,%1,%2,%3}, {%4,%5,%6,%7}, {%8,%9}, {%0,%1,%2,%3};"
        : "+f"(d[0]), "+f"(d[1]), "+f"(d[2]), "+f"(d[3])
        : "r"(a[0]), "r"(a[1]), "r"(a[2]), "r"(a[3]), "r"(b[0]), "r"(b[1]));
}
__device__ __forceinline__ void cp_async16(uint32_t dst, const void* src) {
    asm volatile("cp.async.cg.shared.global [%0], [%1], 16;" :: "r"(dst), "l"(src));
}

// ---------------------------------------------------------------------------
// Prep: split w = r^2 * proto into bf16 h/m/l, compute bias.
// ---------------------------------------------------------------------------
__global__ void prep_kernel(const float* __restrict__ protos,
                            const float* __restrict__ relevance) {
    int p = blockIdx.x;          // 512
    int d = threadIdx.x;         // 128
    float r  = relevance[d];
    float pv = protos[p * DIM + d];
    float w  = r * r * pv;

    __nv_bfloat16 h = __float2bfloat16_rn(w);
    float r1 = w - __bfloat162float(h);
    __nv_bfloat16 m = __float2bfloat16_rn(r1);
    float r2v = r1 - __bfloat162float(m);
    __nv_bfloat16 l = __float2bfloat16_rn(r2v);
    g_w[0][p * DIM + d] = h;
    g_w[1][p * DIM + d] = m;
    g_w[2][p * DIM + d] = l;

    float part = w * pv;
    __shared__ float red[4];
    #pragma unroll
    for (int off = 16; off > 0; off >>= 1)
        part += __shfl_down_sync(0xffffffffu, part, off);
    if ((d & 31) == 0) red[d >> 5] = part;
    __syncthreads();
    if (d == 0) g_bias[p] = -0.5f * (red[0] + red[1] + red[2] + red[3]);
}

// ---------------------------------------------------------------------------
// Main kernel
// ---------------------------------------------------------------------------
extern __shared__ char smem[];

__global__ void __launch_bounds__(256, 1)
grlvq_main(const float* __restrict__ x,
           const float* __restrict__ proto_out,
           float* __restrict__ out) {
    const uint32_t sb = smem_u32(smem);
    const int tid  = threadIdx.x;
    const int wid  = tid >> 5;
    const int lane = tid & 31;
    const int row0 = blockIdx.x * MTILE;
    const int wm = (wid & 3) * 32;     // warp M offset (4 warps)
    const int wn = (wid >> 2) * 32;    // warp N offset within chunk (2 warps)

    // bias -> smem
    for (int i = tid; i < NPROTO; i += 256)
        ((float*)(smem + SM_BIAS))[i] = g_bias[i];

    // ---- issue B chunks 0,1 via cp.async ----
    #define ISSUE_B(c, buf)                                                        \
        do {                                                                       \
            for (int i = tid; i < 3072; i += 256) {                                \
                int mat = i >> 10, rem = i & 1023, rr = rem >> 4, q = rem & 15;    \
                const void* src = &g_w[mat][(size_t)((c) * NCHUNK + rr) * DIM + q * 8]; \
                uint32_t dst = sb + SM_B + (buf) * BBUF + mat * MATB               \
                             + rr * ASTRIDE + q * 16;                              \
                cp_async16(dst, src);                                              \
            }                                                                      \
            asm volatile("cp.async.commit_group;" ::: "memory");                   \
        } while (0)

    ISSUE_B(0, 0);
    ISSUE_B(1, 1);

    // ---- A: load x tile, split into h/m/l bf16, store padded layout ----
    {
        const int r  = tid >> 1;
        const int cb = (tid & 1) * 64;
        const float4* xr = (const float4*)(x + (size_t)(row0 + r) * DIM + cb);
        #pragma unroll
        for (int g = 0; g < 8; g++) {
            float4 v0 = xr[g * 2], v1 = xr[g * 2 + 1];
            float xv[8] = {v0.x, v0.y, v0.z, v0.w, v1.x, v1.y, v1.z, v1.w};
            uint32_t hh[4], mm[4], ll[4];
            #pragma unroll
            for (int q = 0; q < 4; q++) {
                float a0 = xv[2 * q], a1 = xv[2 * q + 1];
                __nv_bfloat16 h0 = __float2bfloat16_rn(a0), h1 = __float2bfloat16_rn(a1);
                float r0 = a0 - __bfloat162float(h0), r1f = a1 - __bfloat162float(h1);
                __nv_bfloat16 m0 = __float2bfloat16_rn(r0), m1 = __float2bfloat16_rn(r1f);
                float s0 = r0 - __bfloat162float(m0), s1 = r1f - __bfloat162float(m1);
                __nv_bfloat16 l0 = __float2bfloat16_rn(s0), l1 = __float2bfloat16_rn(s1);
                hh[q] = ((uint32_t)__bfloat16_as_ushort(h1) << 16) | __bfloat16_as_ushort(h0);
                mm[q] = ((uint32_t)__bfloat16_as_ushort(m1) << 16) | __bfloat16_as_ushort(m0);
                ll[q] = ((uint32_t)__bfloat16_as_ushort(l1) << 16) | __bfloat16_as_ushort(l0);
            }
            uint32_t off = (uint32_t)r * ASTRIDE + (uint32_t)(cb + g * 8) * 2;
            *(uint4*)(smem + SM_A + 0 * ASPLIT + off) = make_uint4(hh[0], hh[1], hh[2], hh[3]);
            *(uint4*)(smem + SM_A + 1 * ASPLIT + off) = make_uint4(mm[0], mm[1], mm[2], mm[3]);
            *(uint4*)(smem + SM_A + 2 * ASPLIT + off) = make_uint4(ll[0], ll[1], ll[2], ll[3]);
        }
    }

    // Per-thread running argmax: 4 local row slots.
    float bestv[4];
    int   besti[4];
    #pragma unroll
    for (int i = 0; i < 4; i++) { bestv[i] = -3.402823466e38f; besti[i] = 0; }

    // ldmatrix base addresses (k-offset added in loop)
    // A: rows = wm + mt*16 + lane%16, khalf = lane/16
    const uint32_t a_row = (uint32_t)(wm + (lane & 15));
    const uint32_t a_kh  = (uint32_t)(lane >> 4) * 16;       // bytes: *8 elems *2B
    // B: rows = wn + np*16 + ((lane>>4)&1)*8 + (lane&7), khalf = (lane>>3)&1
    const uint32_t b_row = (uint32_t)(wn + ((lane >> 4) & 1) * 8 + (lane & 7));
    const uint32_t b_kh  = (uint32_t)((lane >> 3) & 1) * 16;

    static const int TA[6] = {0, 0, 1, 1, 0, 2};
    static const int TB[6] = {0, 1, 0, 1, 2, 0};

    for (int c = 0; c < NCHUNKS; c++) {
        asm volatile("cp.async.wait_group 1;" ::: "memory");
        __syncthreads();
        const uint32_t bbase = sb + SM_B + (c & 1) * BBUF;

        float acc[2][4][4];
        #pragma unroll
        for (int mt = 0; mt < 2; mt++)
            #pragma unroll
            for (int nt = 0; nt < 4; nt++)
                #pragma unroll
                for (int j = 0; j < 4; j++) acc[mt][nt][j] = 0.0f;

        #pragma unroll
        for (int kk = 0; kk < 8; kk++) {
            uint32_t af[3][2][4];
            #pragma unroll
            for (int s = 0; s < 3; s++)
                #pragma unroll
                for (int mt = 0; mt < 2; mt++)
                    ldsm4(af[s][mt],
                          sb + SM_A + s * ASPLIT + (a_row + mt * 16) * ASTRIDE
                          + kk * 32 + a_kh);
            uint32_t bf[3][2][4];
            #pragma unroll
            for (int s = 0; s < 3; s++)
                #pragma unroll
                for (int np = 0; np < 2; np++)
                    ldsm4(bf[s][np],
                          bbase + s * MATB + (b_row + np * 16) * ASTRIDE
                          + kk * 32 + b_kh);
            #pragma unroll
            for (int t = 0; t < 6; t++) {
                #pragma unroll
                for (int mt = 0; mt < 2; mt++)
                    #pragma unroll
                    for (int nt = 0; nt < 4; nt++)
                        mma16816(acc[mt][nt], af[TA[t]][mt],
                                 &bf[TB[t]][nt >> 1][(nt & 1) * 2]);
            }
        }

        // epilogue: bias + running argmax (ascending column order)
        const float* bias_s = (const float*)(smem + SM_BIAS);
        #pragma unroll
        for (int mt = 0; mt < 2; mt++) {
            #pragma unroll
            for (int nt = 0; nt < 4; nt++) {
                const int col = c * NCHUNK + wn + nt * 8 + (lane & 3) * 2;
                float b0 = bias_s[col], b1 = bias_s[col + 1];
                float v0 = acc[mt][nt][0] + b0;   // row r
                float v1 = acc[mt][nt][1] + b1;
                float v2 = acc[mt][nt][2] + b0;   // row r+8
                float v3 = acc[mt][nt][3] + b1;
                int s0 = mt * 2, s1 = mt * 2 + 1;
                if (v0 > bestv[s0]) { bestv[s0] = v0; besti[s0] = col; }
                if (v1 > bestv[s0]) { bestv[s0] = v1; besti[s0] = col + 1; }
                if (v2 > bestv[s1]) { bestv[s1] = v2; besti[s1] = col; }
                if (v3 > bestv[s1]) { bestv[s1] = v3; besti[s1] = col + 1; }
            }
        }

        __syncthreads();
        if (c + 2 < NCHUNKS) ISSUE_B(c + 2, c & 1);
    }

    // ---- cross-thread reduction: 8 candidates per row ----
    float* redv = (float*)(smem + SM_RED);
    int*   redi = (int*)(smem + SM_RED + 4096);
    const int slot = ((wid >> 2) << 2) | (lane & 3);
    #pragma unroll
    for (int sl = 0; sl < 4; sl++) {
        int row = wm + ((sl & 2) << 3) + ((sl & 1) << 3) + (lane >> 2);
        redv[row * 8 + slot] = bestv[sl];
        redi[row * 8 + slot] = besti[sl];
    }
    __syncthreads();

    if (tid < MTILE) {
        float bv = redv[tid * 8];
        int   bi = redi[tid * 8];
        #pragma unroll
        for (int j = 1; j < 8; j++) {
            float v  = redv[tid * 8 + j];
            int   ix = redi[tid * 8 + j];
            if (v > bv || (v == bv && ix < bi)) { bv = v; bi = ix; }
        }
        const float4* po = (const float4*)proto_out;
        float4* o = (float4*)(out + (size_t)(row0 + tid) * ODIM);
        o[0] = po[bi * 2];
        o[1] = po[bi * 2 + 1];
    }
}

// ---------------------------------------------------------------------------
extern "C" void kernel_launch(void* const* d_in, const int* in_sizes, int n_in,
                              void* d_out, int out_size) {
    const float* x         = (const float*)d_in[0];  // [65536,128]
    const float* protos    = (const float*)d_in[1];  // [512,128]
    const float* proto_out = (const float*)d_in[2];  // [512,8]
    const float* relevance = (const float*)d_in[3];  // [128]
    float* out = (float*)d_out;                      // [65536,8]

    prep_kernel<<<NPROTO, DIM>>>(protos, relevance);

    cudaFuncSetAttribute(grlvq_main,
                         cudaFuncAttributeMaxDynamicSharedMemorySize, SMEM_TOTAL);
    grlvq_main<<<BATCH / MTILE, 256, SMEM_TOTAL>>>(x, proto_out, out);
}